// round 2
// baseline (speedup 1.0000x reference)
#include <cuda_runtime.h>
#include <math.h>
#include <float.h>

#define BB 2
#define NN 2048
#define CC 128
#define KK 16
#define BN (BB*NN)
#define PP (BB*NN*KK)
#define EPSF 1e-6f
#define BNEPS 1e-5f

// ---------------- scratch pool ----------------
constexpr long F_SRCD   = 0;
constexpr long F_DSTD   = F_SRCD   + (long)BN*CC;
constexpr long F_NSQS   = F_DSTD   + (long)BN*CC;
constexpr long F_NSQD   = F_NSQS   + BN;
constexpr long F_NRMS   = F_NSQD   + BN;
constexpr long F_NRMD   = F_NRMS   + BN;
constexpr long F_MAXDS  = F_NRMD   + BN;   // contiguous with F_MAXSD (one fill)
constexpr long F_MAXSD  = F_MAXDS  + BN;
constexpr long F_NRM2S  = F_MAXSD  + BN;
constexpr long F_NRM2D  = F_NRM2S  + BN;
constexpr long F_SDC    = F_NRM2D  + BN;
constexpr long F_DSC    = F_SDC    + PP;
constexpr long F_SDN    = F_DSC    + PP;
constexpr long F_DSN    = F_SDN    + PP;
constexpr long F_STATS  = F_DSN    + PP;   // 256 sum (contiguous with sumsq)
constexpr long F_STATQ  = F_STATS  + 256;
constexpr long F_SC     = F_STATQ  + 256;
constexpr long F_SH     = F_SC     + 256;
constexpr long F_IDX    = F_SH     + 256;  // int
constexpr long F_SIDX   = F_IDX    + PP;
constexpr long F_DIDX   = F_SIDX   + PP;
constexpr long F_ATT    = F_DIDX   + PP;
constexpr long F_MB1    = F_ATT    + (long)BN*256;
constexpr long F_MB2    = F_MB1    + (long)BN*256;
constexpr long F_SRCNBR = F_MB2    + (long)BN*256;
constexpr long F_DSTNBR = F_SRCNBR + (long)BN*CC;
constexpr long F_INNER  = F_DSTNBR + (long)BN*CC;
constexpr long F_F      = F_INNER  + (long)BB*NN*NN;
constexpr long F_Y0     = F_F      + (long)PP*272;
constexpr long F_Y1     = F_Y0     + (long)PP*256;
constexpr long F_END    = F_Y1     + (long)PP*256;

__device__ __align__(128) float g_pool[F_END];

__device__ __forceinline__ void atomicMaxF(float* a, float v) {
    if (!(v < 0.f)) atomicMax((int*)a, __float_as_int(v));
    else            atomicMin((unsigned int*)a, __float_as_uint(v));
}

__global__ void k_fill(float* __restrict__ p, float v, int n) {
    int i = blockIdx.x * blockDim.x + threadIdx.x;
    if (i < n) p[i] = v;
}

// [B,C,N] -> [B,N,C] plus |.|^2 and |.|
__global__ void k_transpose_norm(const float* __restrict__ desc, float* __restrict__ dmat,
                                 float* __restrict__ nsq, float* __restrict__ nrm) {
    int bn = blockIdx.x; int b = bn >> 11; int n = bn & (NN - 1);
    int c = threadIdx.x;
    float v = desc[((long)b*CC + c)*NN + n];
    dmat[(long)bn*CC + c] = v;
    float s = v * v;
    #pragma unroll
    for (int o = 16; o > 0; o >>= 1) s += __shfl_down_sync(0xffffffffu, s, o);
    __shared__ float ps[4];
    if ((c & 31) == 0) ps[c >> 5] = s;
    __syncthreads();
    if (c == 0) { float t = ps[0]+ps[1]+ps[2]+ps[3]; nsq[bn] = t; nrm[bn] = sqrtf(t); }
}

__global__ void k_rownorm(const float* __restrict__ dmat, float* __restrict__ nrm) {
    int bn = blockIdx.x; int c = threadIdx.x;
    float v = dmat[(long)bn*CC + c];
    float s = v * v;
    #pragma unroll
    for (int o = 16; o > 0; o >>= 1) s += __shfl_down_sync(0xffffffffu, s, o);
    __shared__ float ps[4];
    if ((c & 31) == 0) ps[c >> 5] = s;
    __syncthreads();
    if (c == 0) nrm[bn] = sqrtf(ps[0]+ps[1]+ps[2]+ps[3]);
}

// ---------------- generic GEMM: C[P,O] = act(A)[P,K] * B[O,K]^T ----------------
#define GTILE 64
#define GK 16
#define GPAD 4
__global__ void k_gemm(const float* __restrict__ A, const float* __restrict__ Bm,
                       float* __restrict__ Cm, int P, int O, int Kd,
                       long sA, long sB, long sC,
                       const float* __restrict__ scA, const float* __restrict__ shA,
                       float* __restrict__ statS, float* __restrict__ statQ) {
    A  += (long)blockIdx.z * sA;
    Bm += (long)blockIdx.z * sB;
    Cm += (long)blockIdx.z * sC;
    __shared__ __align__(16) float As[GK][GTILE + GPAD];
    __shared__ __align__(16) float Bs[GK][GTILE + GPAD];
    const int tx = threadIdx.x, ty = threadIdx.y;
    const int tid = ty * 16 + tx;
    const int rowBase = blockIdx.y * GTILE;
    const int colBase = blockIdx.x * GTILE;
    float acc[4][4] = {};
    const int nk = (Kd + GK - 1) / GK;
    const bool aff = (scA != nullptr);
    for (int kt = 0; kt < nk; kt++) {
        const int k0 = kt * GK;
        #pragma unroll
        for (int e = 0; e < 4; e++) {
            int lin = e * 256 + tid;
            int r = lin >> 4;
            int k = lin & 15;
            int gk = k0 + k;
            float va = 0.f, vb = 0.f;
            if (gk < Kd) {
                va = A[(long)(rowBase + r) * Kd + gk];
                if (aff) va = fmaxf(va * scA[gk] + shA[gk], 0.f);
                vb = Bm[(long)(colBase + r) * Kd + gk];
            }
            As[k][r] = va;
            Bs[k][r] = vb;
        }
        __syncthreads();
        #pragma unroll
        for (int kk = 0; kk < GK; kk++) {
            float4 a4 = *reinterpret_cast<const float4*>(&As[kk][ty * 4]);
            float4 b4 = *reinterpret_cast<const float4*>(&Bs[kk][tx * 4]);
            float a[4] = {a4.x, a4.y, a4.z, a4.w};
            float bq[4] = {b4.x, b4.y, b4.z, b4.w};
            #pragma unroll
            for (int i = 0; i < 4; i++)
                #pragma unroll
                for (int j = 0; j < 4; j++)
                    acc[i][j] += a[i] * bq[j];
        }
        __syncthreads();
    }
    #pragma unroll
    for (int i = 0; i < 4; i++) {
        int r = rowBase + ty * 4 + i;
        #pragma unroll
        for (int j = 0; j < 4; j++)
            Cm[(long)r * O + colBase + tx * 4 + j] = acc[i][j];
    }
    if (statS) {
        __shared__ float cs[GTILE], cq[GTILE];
        if (tid < GTILE) { cs[tid] = 0.f; cq[tid] = 0.f; }
        __syncthreads();
        #pragma unroll
        for (int j = 0; j < 4; j++) {
            float s = 0.f, q = 0.f;
            #pragma unroll
            for (int i = 0; i < 4; i++) { s += acc[i][j]; q += acc[i][j]*acc[i][j]; }
            atomicAdd(&cs[tx*4+j], s);
            atomicAdd(&cq[tx*4+j], q);
        }
        __syncthreads();
        if (tid < GTILE) {
            atomicAdd(&statS[colBase + tid], cs[tid]);
            atomicAdd(&statQ[colBase + tid], cq[tid]);
        }
    }
}

__global__ void k_finalize(const float* __restrict__ statS, const float* __restrict__ statQ,
                           const float* __restrict__ g, const float* __restrict__ bb,
                           float* __restrict__ sc, float* __restrict__ sh, int O, float invP) {
    int o = blockIdx.x * blockDim.x + threadIdx.x;
    if (o < O) {
        float mu  = statS[o] * invP;
        float var = fmaxf(statQ[o] * invP - mu * mu, 0.f);
        float s   = g[o] * rsqrtf(var + BNEPS);
        sc[o] = s;
        sh[o] = bb[o] - mu * s;
    }
}

// row/col maxes of cosine matrix. inner[b][n(src)][m(dst)]
__global__ void k_cosmax(const float* __restrict__ inner, const float* __restrict__ nrmS,
                         const float* __restrict__ nrmD, float* __restrict__ maxDS,
                         float* __restrict__ maxSD) {
    int b = blockIdx.z;
    int n = blockIdx.y * 32 + threadIdx.y;
    int m = blockIdx.x * 32 + threadIdx.x;
    float v  = inner[(long)b*NN*NN + (long)n*NN + m];
    float cs = v / (nrmD[b*NN + m] * nrmS[b*NN + n] + EPSF);
    float r = cs;
    #pragma unroll
    for (int o = 16; o > 0; o >>= 1) r = fmaxf(r, __shfl_down_sync(0xffffffffu, r, o));
    if (threadIdx.x == 0) atomicMaxF(&maxDS[b*NN + n], r);
    __shared__ float cm[32];
    int tid = threadIdx.y * 32 + threadIdx.x;
    if (tid < 32) cm[tid] = -3.4e38f;
    __syncthreads();
    atomicMaxF(&cm[threadIdx.x], cs);
    __syncthreads();
    if (threadIdx.y == 0) atomicMaxF(&maxSD[b*NN + m], cm[threadIdx.x]);
}

// top-16 smallest from shared d2[NN], 256 threads
__device__ void select_topk(float* d2, int* outIdx) {
    __shared__ float rv[8];
    __shared__ int   ri[8];
    int tid = threadIdx.x, lane = tid & 31, w = tid >> 5;
    for (int kk = 0; kk < KK; kk++) {
        float best = 3.4e38f; int bi = 0;
        for (int m = tid; m < NN; m += 256) {
            float v = d2[m];
            if (v < best) { best = v; bi = m; }
        }
        #pragma unroll
        for (int o = 16; o > 0; o >>= 1) {
            float ov = __shfl_down_sync(0xffffffffu, best, o);
            int   oi = __shfl_down_sync(0xffffffffu, bi, o);
            if (ov < best || (ov == best && oi < bi)) { best = ov; bi = oi; }
        }
        if (lane == 0) { rv[w] = best; ri[w] = bi; }
        __syncthreads();
        if (tid == 0) {
            float bv = rv[0]; int bj = ri[0];
            #pragma unroll
            for (int i = 1; i < 8; i++)
                if (rv[i] < bv || (rv[i] == bv && ri[i] < bj)) { bv = rv[i]; bj = ri[i]; }
            outIdx[kk] = bj;
            d2[bj] = 3.4e38f;
        }
        __syncthreads();
    }
}

__global__ void k_knn_desc(const float* __restrict__ inner, const float* __restrict__ nsqS,
                           const float* __restrict__ nsqD, int* __restrict__ idxOut) {
    int n = blockIdx.x, b = blockIdx.y;
    __shared__ float d2[NN];
    const float* row = inner + (long)b*NN*NN + (long)n*NN;
    float q = nsqS[b*NN + n];
    for (int m = threadIdx.x; m < NN; m += 256) d2[m] = q + nsqD[b*NN + m] - 2.f * row[m];
    __syncthreads();
    select_topk(d2, idxOut + ((long)b*NN + n) * KK);
}

__global__ void k_knn_xyz(const float* __restrict__ xyz, int* __restrict__ idxOut) {
    int n = blockIdx.x, b = blockIdx.y;
    __shared__ float d2[NN];
    long base = (long)b * NN * 3;
    float qx = xyz[base + (long)n*3], qy = xyz[base + (long)n*3+1], qz = xyz[base + (long)n*3+2];
    float qq = qx*qx + qy*qy + qz*qz;
    for (int m = threadIdx.x; m < NN; m += 256) {
        float rx = xyz[base + (long)m*3], ry = xyz[base + (long)m*3+1], rz = xyz[base + (long)m*3+2];
        d2[m] = qq + rx*rx + ry*ry + rz*rz - 2.f*(qx*rx + qy*ry + qz*rz);
    }
    __syncthreads();
    select_topk(d2, idxOut + ((long)b*NN + n) * KK);
}

__global__ void k_simgather(const float* __restrict__ inner, const float* __restrict__ nrmS,
                            const float* __restrict__ nrmD, const float* __restrict__ maxDS,
                            const float* __restrict__ maxSD, const int* __restrict__ idx,
                            float* __restrict__ outSD, float* __restrict__ outDS) {
    int t = blockIdx.x * 256 + threadIdx.x;
    if (t >= PP) return;
    int b = t / (NN * KK);
    int n = (t / KK) & (NN - 1);
    int m = idx[t];
    float v  = inner[(long)b*NN*NN + (long)n*NN + m];
    float cs = v / (nrmD[b*NN + m] * nrmS[b*NN + n] + EPSF);
    outSD[t] = cs / (maxDS[b*NN + n] + EPSF);
    outDS[t] = cs / (maxSD[b*NN + m] + EPSF);
}

// nbr conv input: [knn_feats(C), rela(3), dist(1)]
__global__ void k_build_nbr_f(const float* __restrict__ xyz, const float* __restrict__ dmat,
                              const int* __restrict__ idx, float* __restrict__ f) {
    int p = blockIdx.x;
    int n = (p / KK) & (NN - 1);
    int b = p / (NN * KK);
    int m = idx[p];
    const float* dr = dmat + ((long)b*NN + m) * CC;
    float* fo = f + (long)p * 132;
    int tid = threadIdx.x;
    fo[tid] = dr[tid];
    if (tid == 0) {
        long qb = ((long)b*NN + n) * 3, rb = ((long)b*NN + m) * 3;
        float rx = xyz[rb]-xyz[qb], ry = xyz[rb+1]-xyz[qb+1], rz = xyz[rb+2]-xyz[qb+2];
        fo[128] = rx; fo[129] = ry; fo[130] = rz; fo[131] = sqrtf(rx*rx+ry*ry+rz*rz);
    }
}

__global__ void k_nbr_final(const float* __restrict__ yraw, const float* __restrict__ sc,
                            const float* __restrict__ sh, const int* __restrict__ idx,
                            const float* __restrict__ dmat, float* __restrict__ outN) {
    int bn = blockIdx.x, tid = threadIdx.x; // 256
    __shared__ float fe[KK][CC];
    __shared__ float mk[KK], wgt[KK];
    __shared__ int sid[KK];
    if (tid < KK) sid[tid] = idx[(long)bn*KK + tid];
    for (int t = tid; t < KK * CC; t += 256) {
        int k = t >> 7, c = t & 127;
        float v = yraw[((long)bn*KK + k) * CC + c];
        fe[k][c] = fmaxf(v * sc[c] + sh[c], 0.f);
    }
    __syncthreads();
    int w = tid >> 5, lane = tid & 31;
    for (int kk = w; kk < KK; kk += 8) {
        float mx = -3.4e38f;
        for (int c = lane; c < CC; c += 32) mx = fmaxf(mx, fe[kk][c]);
        #pragma unroll
        for (int o = 16; o > 0; o >>= 1) mx = fmaxf(mx, __shfl_down_sync(0xffffffffu, mx, o));
        if (lane == 0) mk[kk] = mx;
    }
    __syncthreads();
    if (tid == 0) {
        float m = -3.4e38f;
        for (int k = 0; k < KK; k++) m = fmaxf(m, mk[k]);
        float s = 0.f;
        for (int k = 0; k < KK; k++) { float e = expf(mk[k]-m); wgt[k] = e; s += e; }
        float r = 1.f / s;
        for (int k = 0; k < KK; k++) wgt[k] *= r;
    }
    __syncthreads();
    if (tid < CC) {
        int b = bn >> 11;
        float a = 0.f;
        #pragma unroll
        for (int k = 0; k < KK; k++) a += wgt[k] * dmat[((long)b*NN + sid[k]) * CC + tid];
        outN[(long)bn*CC + tid] = a;
    }
}

// main feats build (272 ch)
__global__ void k_build_feats(const float* __restrict__ src_xyz, const float* __restrict__ dst_xyz,
                              const float* __restrict__ srcd, const float* __restrict__ dstd,
                              const float* __restrict__ srcw, const float* __restrict__ dstw,
                              const float* __restrict__ sdc, const float* __restrict__ dsc,
                              const float* __restrict__ sdn, const float* __restrict__ dsn,
                              const int* __restrict__ idx, float* __restrict__ feats) {
    int p = blockIdx.x;
    int n = (p / KK) & (NN - 1);
    int b = p / (NN * KK);
    int m = idx[p];
    float* fo = feats + (long)p * 272;
    int tid = threadIdx.x;
    fo[10 + tid]  = srcd[((long)b*NN + n) * CC + tid];
    fo[138 + tid] = dstd[((long)b*NN + m) * CC + tid];
    if (tid == 0) {
        long qb = ((long)b*NN + n) * 3, rb = ((long)b*NN + m) * 3;
        float sx = src_xyz[qb], sy = src_xyz[qb+1], sz = src_xyz[qb+2];
        float kx = dst_xyz[rb], ky = dst_xyz[rb+1], kz = dst_xyz[rb+2];
        float rx = kx-sx, ry = ky-sy, rz = kz-sz;
        fo[0]=rx; fo[1]=ry; fo[2]=rz; fo[3]=sqrtf(rx*rx+ry*ry+rz*rz);
        fo[4]=sx; fo[5]=sy; fo[6]=sz; fo[7]=kx; fo[8]=ky; fo[9]=kz;
        fo[266]=srcw[b*NN+n]; fo[267]=dstw[b*NN+m];
        fo[268]=sdc[p]; fo[269]=dsc[p]; fo[270]=sdn[p]; fo[271]=dsn[p];
    }
}

__global__ void k_attention(const float* __restrict__ yraw, const float* __restrict__ sc,
                            const float* __restrict__ sh, const int* __restrict__ idx,
                            const float* __restrict__ dst_xyz,
                            float* __restrict__ outC, float* __restrict__ att) {
    int bn = blockIdx.x, tid = threadIdx.x; // 256
    __shared__ float fe[KK][256];
    __shared__ float mk[KK], wgt[KK];
    __shared__ int sid[KK];
    if (tid < KK) sid[tid] = idx[(long)bn*KK + tid];
    float s = sc[tid], h = sh[tid];
    #pragma unroll
    for (int k = 0; k < KK; k++) {
        float v = yraw[((long)bn*KK + k) * 256 + tid];
        fe[k][tid] = fmaxf(v * s + h, 0.f);
    }
    __syncthreads();
    int w = tid >> 5, lane = tid & 31;
    for (int kk = w; kk < KK; kk += 8) {
        float mx = -3.4e38f;
        for (int c = lane; c < 256; c += 32) mx = fmaxf(mx, fe[kk][c]);
        #pragma unroll
        for (int o = 16; o > 0; o >>= 1) mx = fmaxf(mx, __shfl_down_sync(0xffffffffu, mx, o));
        if (lane == 0) mk[kk] = mx;
    }
    __syncthreads();
    if (tid == 0) {
        float m = -3.4e38f;
        for (int k = 0; k < KK; k++) m = fmaxf(m, mk[k]);
        float ssum = 0.f;
        for (int k = 0; k < KK; k++) { float e = expf(mk[k]-m); wgt[k] = e; ssum += e; }
        float r = 1.f / ssum;
        for (int k = 0; k < KK; k++) wgt[k] *= r;
    }
    __syncthreads();
    float a = 0.f;
    #pragma unroll
    for (int k = 0; k < KK; k++) a += wgt[k] * fe[k][tid];
    att[(long)bn * 256 + tid] = a;
    if (tid < 3) {
        int b = bn >> 11;
        float cg = 0.f;
        #pragma unroll
        for (int k = 0; k < KK; k++)
            cg += wgt[k] * dst_xyz[((long)b*NN + sid[k]) * 3 + tid];
        outC[(long)bn * 3 + tid] = cg;
    }
}

__global__ void k_mlp3(const float* __restrict__ yraw, const float* __restrict__ sc,
                       const float* __restrict__ sh, const float* __restrict__ w3,
                       const float* __restrict__ b3, float* __restrict__ outw) {
    int bn = blockIdx.x, tid = threadIdx.x; // 256
    float v = fmaxf(yraw[(long)bn*256 + tid] * sc[tid] + sh[tid], 0.f) * w3[tid];
    #pragma unroll
    for (int o = 16; o > 0; o >>= 1) v += __shfl_down_sync(0xffffffffu, v, o);
    __shared__ float ps[8];
    if ((tid & 31) == 0) ps[tid >> 5] = v;
    __syncthreads();
    if (tid == 0) {
        float s2 = 0.f;
        #pragma unroll
        for (int i = 0; i < 8; i++) s2 += ps[i];
        outw[bn] = 1.f / (1.f + expf(-(s2 + b3[0])));
    }
}

// ---------------- host side ----------------
static void conv_bn(const float* A, const float* W, float* Y, int P, int O, int Kd,
                    bool aff, const float* g, const float* bb,
                    float* statS, float* sc, float* sh) {
    k_fill<<<2, 256>>>(statS, 0.f, 512);
    k_gemm<<<dim3(O/64, P/64, 1), dim3(16, 16)>>>(A, W, Y, P, O, Kd, 0, 0, 0,
        aff ? sc : nullptr, aff ? sh : nullptr, statS, statS + 256);
    k_finalize<<<1, 256>>>(statS, statS + 256, g, bb, sc, sh, O, 1.f / (float)P);
}

extern "C" void kernel_launch(void* const* d_in, const int* in_sizes, int n_in,
                              void* d_out, int out_size) {
    const float* src_xyz  = (const float*)d_in[0];
    const float* src_desc = (const float*)d_in[1];
    const float* dst_xyz  = (const float*)d_in[2];
    const float* dst_desc = (const float*)d_in[3];
    const float* src_w    = (const float*)d_in[4];
    const float* dst_w    = (const float*)d_in[5];
    const float* c1_W0 = (const float*)d_in[6];
    const float* c1_W  = (const float*)d_in[7];
    const float* c1_g  = (const float*)d_in[8];
    const float* c1_b  = (const float*)d_in[9];
    const float* c2_W0 = (const float*)d_in[10];
    const float* c2_W  = (const float*)d_in[11];
    const float* c2_g  = (const float*)d_in[12];
    const float* c2_b  = (const float*)d_in[13];
    const float* m1_W  = (const float*)d_in[14];
    const float* m1_g  = (const float*)d_in[16];
    const float* m1_b  = (const float*)d_in[17];
    const float* m2_W  = (const float*)d_in[18];
    const float* m2_g  = (const float*)d_in[20];
    const float* m2_b  = (const float*)d_in[21];
    const float* m3_W  = (const float*)d_in[22];
    const float* m3_b  = (const float*)d_in[23];

    float* base = nullptr;
    cudaGetSymbolAddress((void**)&base, g_pool);
    float* srcd   = base + F_SRCD;
    float* dstd   = base + F_DSTD;
    float* nsqS   = base + F_NSQS;
    float* nsqD   = base + F_NSQD;
    float* nrmS   = base + F_NRMS;
    float* nrmD   = base + F_NRMD;
    float* maxDS  = base + F_MAXDS;
    float* maxSD  = base + F_MAXSD;
    float* nrm2S  = base + F_NRM2S;
    float* nrm2D  = base + F_NRM2D;
    float* sdc    = base + F_SDC;
    float* dsc    = base + F_DSC;
    float* sdn    = base + F_SDN;
    float* dsn    = base + F_DSN;
    float* statS  = base + F_STATS;
    float* sc     = base + F_SC;
    float* sh     = base + F_SH;
    int*   idx    = (int*)(base + F_IDX);
    int*   sidx   = (int*)(base + F_SIDX);
    int*   didx   = (int*)(base + F_DIDX);
    float* att    = base + F_ATT;
    float* mb1    = base + F_MB1;
    float* mb2    = base + F_MB2;
    float* srcnbr = base + F_SRCNBR;
    float* dstnbr = base + F_DSTNBR;
    float* inner  = base + F_INNER;
    float* fbuf   = base + F_F;
    float* y0     = base + F_Y0;
    float* y1     = base + F_Y1;
    float* outC   = (float*)d_out;
    float* outW   = (float*)d_out + (long)BB*NN*3;

    // A: transpose + norms
    k_transpose_norm<<<BN, 128>>>(src_desc, srcd, nsqS, nrmS);
    k_transpose_norm<<<BN, 128>>>(dst_desc, dstd, nsqD, nrmD);

    // inner = src . dst (per batch), then cos maxes + KNN + sims
    k_gemm<<<dim3(32, 32, 2), dim3(16, 16)>>>(srcd, dstd, inner, NN, NN, CC,
        (long)NN*CC, (long)NN*CC, (long)NN*NN, nullptr, nullptr, nullptr, nullptr);
    k_fill<<<32, 256>>>(maxDS, -3.4e38f, 2*BN);
    k_cosmax<<<dim3(64, 64, 2), dim3(32, 32)>>>(inner, nrmS, nrmD, maxDS, maxSD);
    k_knn_desc<<<dim3(NN, BB), 256>>>(inner, nsqS, nsqD, idx);
    k_simgather<<<PP/256, 256>>>(inner, nrmS, nrmD, maxDS, maxSD, idx, sdc, dsc);

    // B: neighborhood descriptors (src then dst)
    k_knn_xyz<<<dim3(NN, BB), 256>>>(src_xyz, sidx);
    k_knn_xyz<<<dim3(NN, BB), 256>>>(dst_xyz, didx);
    const float* c2W1 = c2_W;
    const float* c2W2 = c2_W + CC*CC;
    for (int cloud = 0; cloud < 2; cloud++) {
        const float* xyz  = cloud ? dst_xyz : src_xyz;
        const float* dmat = cloud ? dstd : srcd;
        int* kidx         = cloud ? didx : sidx;
        float* outN       = cloud ? dstnbr : srcnbr;
        k_build_nbr_f<<<PP, 128>>>(xyz, dmat, kidx, fbuf);
        conv_bn(fbuf, c2_W0, y0, PP, CC, 132, false, c2_g,        c2_b,        statS, sc, sh);
        conv_bn(y0,   c2W1,  y1, PP, CC, CC,  true,  c2_g + CC,   c2_b + CC,   statS, sc, sh);
        conv_bn(y1,   c2W2,  y0, PP, CC, CC,  true,  c2_g + 2*CC, c2_b + 2*CC, statS, sc, sh);
        k_nbr_final<<<BN, 256>>>(y0, sc, sh, kidx, dmat, outN);
    }

    // nbr cosine sims (reuse inner + maxes)
    k_rownorm<<<BN, 128>>>(srcnbr, nrm2S);
    k_rownorm<<<BN, 128>>>(dstnbr, nrm2D);
    k_gemm<<<dim3(32, 32, 2), dim3(16, 16)>>>(srcnbr, dstnbr, inner, NN, NN, CC,
        (long)NN*CC, (long)NN*CC, (long)NN*NN, nullptr, nullptr, nullptr, nullptr);
    k_fill<<<32, 256>>>(maxDS, -3.4e38f, 2*BN);
    k_cosmax<<<dim3(64, 64, 2), dim3(32, 32)>>>(inner, nrm2S, nrm2D, maxDS, maxSD);
    k_simgather<<<PP/256, 256>>>(inner, nrm2S, nrm2D, maxDS, maxSD, idx, sdn, dsn);

    // C: main feature conv + attention
    k_build_feats<<<PP, 128>>>(src_xyz, dst_xyz, srcd, dstd, src_w, dst_w,
                               sdc, dsc, sdn, dsn, idx, fbuf);
    const float* c1W1 = c1_W;
    const float* c1W2 = c1_W + 256*256;
    conv_bn(fbuf, c1_W0, y0, PP, 256, 272, false, c1_g,        c1_b,        statS, sc, sh);
    conv_bn(y0,   c1W1,  y1, PP, 256, 256, true,  c1_g + 256,  c1_b + 256,  statS, sc, sh);
    conv_bn(y1,   c1W2,  y0, PP, 256, 256, true,  c1_g + 512,  c1_b + 512,  statS, sc, sh);
    k_attention<<<BN, 256>>>(y0, sc, sh, idx, dst_xyz, outC, att);

    // D: MLP head
    conv_bn(att, m1_W, mb1, BN, 256, 256, false, m1_g, m1_b, statS, sc, sh);
    conv_bn(mb1, m2_W, mb2, BN, 256, 256, true,  m2_g, m2_b, statS, sc, sh);
    k_mlp3<<<BN, 256>>>(mb2, sc, sh, m3_W, m3_b, outW);
}

// round 3
// speedup vs baseline: 1.2170x; 1.2170x over previous
#include <cuda_runtime.h>
#include <math.h>
#include <float.h>

#define BB 2
#define NN 2048
#define CC 128
#define KK 16
#define BN (BB*NN)
#define PP (BB*NN*KK)
#define EPSF 1e-6f
#define BNEPS 1e-5f

// ---------------- scratch pool ----------------
constexpr long F_SRCD   = 0;
constexpr long F_DSTD   = F_SRCD   + (long)BN*CC;
constexpr long F_NSQS   = F_DSTD   + (long)BN*CC;
constexpr long F_NSQD   = F_NSQS   + BN;
constexpr long F_NRMS   = F_NSQD   + BN;
constexpr long F_NRMD   = F_NRMS   + BN;
constexpr long F_MAXDS  = F_NRMD   + BN;   // contiguous with F_MAXSD
constexpr long F_MAXSD  = F_MAXDS  + BN;
constexpr long F_NRM2S  = F_MAXSD  + BN;
constexpr long F_NRM2D  = F_NRM2S  + BN;
constexpr long F_SDC    = F_NRM2D  + BN;
constexpr long F_DSC    = F_SDC    + PP;
constexpr long F_SDN    = F_DSC    + PP;
constexpr long F_DSN    = F_SDN    + PP;
constexpr long F_STATS  = F_DSN    + PP;   // 256 sum (contiguous with sumsq)
constexpr long F_STATQ  = F_STATS  + 256;
constexpr long F_SC     = F_STATQ  + 256;
constexpr long F_SH     = F_SC     + 256;
constexpr long F_W2P    = F_SH     + 256;          // padded c2_W0 [128][136]
constexpr long F_IDX    = F_W2P    + 128*136;      // int
constexpr long F_SIDX   = F_IDX    + PP;
constexpr long F_DIDX   = F_SIDX   + PP;
constexpr long F_ATT    = F_DIDX   + PP;
constexpr long F_MB1    = F_ATT    + (long)BN*256;
constexpr long F_MB2    = F_MB1    + (long)BN*256;
constexpr long F_SRCNBR = F_MB2    + (long)BN*256;
constexpr long F_DSTNBR = F_SRCNBR + (long)BN*CC;
constexpr long F_INNER  = F_DSTNBR + (long)BN*CC;
constexpr long F_F      = F_INNER  + (long)BB*NN*NN;
constexpr long F_Y0     = F_F      + (long)PP*272;
constexpr long F_Y1     = F_Y0     + (long)PP*256;
constexpr long F_END    = F_Y1     + (long)PP*256;

__device__ __align__(128) float g_pool[F_END];

__device__ __forceinline__ void atomicMaxF(float* a, float v) {
    if (!(v < 0.f)) atomicMax((int*)a, __float_as_int(v));
    else            atomicMin((unsigned int*)a, __float_as_uint(v));
}

__global__ void k_fill(float* __restrict__ p, float v, int n) {
    int i = blockIdx.x * blockDim.x + threadIdx.x;
    if (i < n) p[i] = v;
}

__global__ void k_pad_w(const float* __restrict__ W, float* __restrict__ Wp) {
    int o = blockIdx.x; int k = threadIdx.x; // 136 threads
    Wp[o * 136 + k] = (k < 132) ? W[o * 132 + k] : 0.f;
}

// [B,C,N] -> [B,N,C] plus |.|^2 and |.|
__global__ void k_transpose_norm(const float* __restrict__ desc, float* __restrict__ dmat,
                                 float* __restrict__ nsq, float* __restrict__ nrm) {
    int bn = blockIdx.x; int b = bn >> 11; int n = bn & (NN - 1);
    int c = threadIdx.x;
    float v = desc[((long)b*CC + c)*NN + n];
    dmat[(long)bn*CC + c] = v;
    float s = v * v;
    #pragma unroll
    for (int o = 16; o > 0; o >>= 1) s += __shfl_down_sync(0xffffffffu, s, o);
    __shared__ float ps[4];
    if ((c & 31) == 0) ps[c >> 5] = s;
    __syncthreads();
    if (c == 0) { float t = ps[0]+ps[1]+ps[2]+ps[3]; nsq[bn] = t; nrm[bn] = sqrtf(t); }
}

__global__ void k_rownorm(const float* __restrict__ dmat, float* __restrict__ nrm) {
    int bn = blockIdx.x; int c = threadIdx.x;
    float v = dmat[(long)bn*CC + c];
    float s = v * v;
    #pragma unroll
    for (int o = 16; o > 0; o >>= 1) s += __shfl_down_sync(0xffffffffu, s, o);
    __shared__ float ps[4];
    if ((c & 31) == 0) ps[c >> 5] = s;
    __syncthreads();
    if (c == 0) nrm[bn] = sqrtf(ps[0]+ps[1]+ps[2]+ps[3]);
}

// ---------------- GEMM: C[P,O] = act(A)[P,K] * B[O,K]^T ----------------
// 128x128 tile, 8x8 microtile, double-buffered smem, K % 8 == 0 required.
#define BT 128
#define GKS 8
#define SPAD 4

__device__ __forceinline__ float4 ld_aff(const float* __restrict__ p,
                                         const float* __restrict__ scA,
                                         const float* __restrict__ shA,
                                         int kb, bool aff) {
    float4 v = *reinterpret_cast<const float4*>(p);
    if (aff) {
        v.x = fmaxf(v.x * scA[kb+0] + shA[kb+0], 0.f);
        v.y = fmaxf(v.y * scA[kb+1] + shA[kb+1], 0.f);
        v.z = fmaxf(v.z * scA[kb+2] + shA[kb+2], 0.f);
        v.w = fmaxf(v.w * scA[kb+3] + shA[kb+3], 0.f);
    }
    return v;
}

__global__ __launch_bounds__(256)
void k_gemm(const float* __restrict__ A, const float* __restrict__ Bm,
            float* __restrict__ Cm, int P, int O, int Kd,
            long sA, long sB, long sC,
            const float* __restrict__ scA, const float* __restrict__ shA,
            float* __restrict__ statS, float* __restrict__ statQ) {
    A  += (long)blockIdx.z * sA;
    Bm += (long)blockIdx.z * sB;
    Cm += (long)blockIdx.z * sC;
    __shared__ __align__(16) float As[2][GKS][BT + SPAD];
    __shared__ __align__(16) float Bs[2][GKS][BT + SPAD];
    const int tx = threadIdx.x, ty = threadIdx.y;
    const int tid = ty * 16 + tx;
    const int rowBase = blockIdx.y * BT;
    const int colBase = blockIdx.x * BT;
    const int lr = tid >> 1;          // 0..127
    const int lk = (tid & 1) * 4;     // 0 or 4
    const bool aff = (scA != nullptr);
    const float* Aptr = A  + (long)(rowBase + lr) * Kd + lk;
    const float* Bptr = Bm + (long)(colBase + lr) * Kd + lk;
    float acc[8][8] = {};
    const int nk = Kd / GKS;

    // prologue: tile 0
    {
        float4 av = ld_aff(Aptr, scA, shA, lk, aff);
        float4 bv = *reinterpret_cast<const float4*>(Bptr);
        As[0][lk+0][lr] = av.x; As[0][lk+1][lr] = av.y;
        As[0][lk+2][lr] = av.z; As[0][lk+3][lr] = av.w;
        Bs[0][lk+0][lr] = bv.x; Bs[0][lk+1][lr] = bv.y;
        Bs[0][lk+2][lr] = bv.z; Bs[0][lk+3][lr] = bv.w;
    }
    __syncthreads();

    for (int kt = 0; kt < nk; kt++) {
        const int cur = kt & 1;
        float4 av2, bv2;
        const bool more = (kt + 1 < nk);
        if (more) {
            av2 = ld_aff(Aptr + (kt+1)*GKS, scA, shA, (kt+1)*GKS + lk, aff);
            bv2 = *reinterpret_cast<const float4*>(Bptr + (kt+1)*GKS);
        }
        #pragma unroll
        for (int kk = 0; kk < GKS; kk++) {
            float4 a0 = *reinterpret_cast<const float4*>(&As[cur][kk][ty*4]);
            float4 a1 = *reinterpret_cast<const float4*>(&As[cur][kk][ty*4+64]);
            float4 b0 = *reinterpret_cast<const float4*>(&Bs[cur][kk][tx*4]);
            float4 b1 = *reinterpret_cast<const float4*>(&Bs[cur][kk][tx*4+64]);
            float a[8] = {a0.x,a0.y,a0.z,a0.w,a1.x,a1.y,a1.z,a1.w};
            float b[8] = {b0.x,b0.y,b0.z,b0.w,b1.x,b1.y,b1.z,b1.w};
            #pragma unroll
            for (int i = 0; i < 8; i++)
                #pragma unroll
                for (int j = 0; j < 8; j++)
                    acc[i][j] += a[i] * b[j];
        }
        if (more) {
            const int nb = cur ^ 1;
            As[nb][lk+0][lr] = av2.x; As[nb][lk+1][lr] = av2.y;
            As[nb][lk+2][lr] = av2.z; As[nb][lk+3][lr] = av2.w;
            Bs[nb][lk+0][lr] = bv2.x; Bs[nb][lk+1][lr] = bv2.y;
            Bs[nb][lk+2][lr] = bv2.z; Bs[nb][lk+3][lr] = bv2.w;
        }
        __syncthreads();
    }

    // store C
    #pragma unroll
    for (int i = 0; i < 8; i++) {
        long r = rowBase + ty*4 + ((i < 4) ? i : 64 + i - 4);
        float4 v0 = {acc[i][0], acc[i][1], acc[i][2], acc[i][3]};
        float4 v1 = {acc[i][4], acc[i][5], acc[i][6], acc[i][7]};
        *reinterpret_cast<float4*>(&Cm[r * O + colBase + tx*4])      = v0;
        *reinterpret_cast<float4*>(&Cm[r * O + colBase + tx*4 + 64]) = v1;
    }

    if (statS) {
        __shared__ float cs[BT], cq[BT];
        if (tid < BT) { cs[tid] = 0.f; cq[tid] = 0.f; }
        __syncthreads();
        #pragma unroll
        for (int j = 0; j < 8; j++) {
            int col = (j < 4) ? tx*4 + j : 64 + tx*4 + j - 4;
            float s = 0.f, q = 0.f;
            #pragma unroll
            for (int i = 0; i < 8; i++) { float v = acc[i][j]; s += v; q += v*v; }
            atomicAdd(&cs[col], s);
            atomicAdd(&cq[col], q);
        }
        __syncthreads();
        if (tid < BT) {
            atomicAdd(&statS[colBase + tid], cs[tid]);
            atomicAdd(&statQ[colBase + tid], cq[tid]);
        }
    }
}

__global__ void k_finalize(const float* __restrict__ statSin, const float* __restrict__ statQin,
                           const float* __restrict__ g, const float* __restrict__ bb,
                           float* __restrict__ sc, float* __restrict__ sh, int O, float invP) {
    int o = blockIdx.x * blockDim.x + threadIdx.x;
    if (o < O) {
        float mu  = statSin[o] * invP;
        float var = fmaxf(statQin[o] * invP - mu * mu, 0.f);
        float s   = g[o] * rsqrtf(var + BNEPS);
        sc[o] = s;
        sh[o] = bb[o] - mu * s;
        // re-zero stats for next layer (initial zero done once per launch)
        ((float*)statSin)[o] = 0.f;
        ((float*)statQin)[o] = 0.f;
    }
}

// row maxes of cosine matrix (max over dst m for each src n)
__global__ void k_rowmax(const float* __restrict__ inner, const float* __restrict__ nrmS,
                         const float* __restrict__ nrmD, float* __restrict__ maxDS) {
    int b = blockIdx.y, n = blockIdx.x;
    const float* row = inner + (long)b*NN*NN + (long)n*NN;
    float ns = nrmS[b*NN + n];
    float mx = -3.4e38f;
    for (int m = threadIdx.x; m < NN; m += 256)
        mx = fmaxf(mx, row[m] / (nrmD[b*NN + m] * ns + EPSF));
    #pragma unroll
    for (int o = 16; o > 0; o >>= 1) mx = fmaxf(mx, __shfl_down_sync(0xffffffffu, mx, o));
    __shared__ float ps[8];
    if ((threadIdx.x & 31) == 0) ps[threadIdx.x >> 5] = mx;
    __syncthreads();
    if (threadIdx.x == 0) {
        float r = ps[0];
        #pragma unroll
        for (int i = 1; i < 8; i++) r = fmaxf(r, ps[i]);
        maxDS[b*NN + n] = r;
    }
}

// col maxes (max over src n for each dst m), chunked over n
__global__ void k_colmax(const float* __restrict__ inner, const float* __restrict__ nrmS,
                         const float* __restrict__ nrmD, float* __restrict__ maxSD) {
    int b = blockIdx.z;
    int m = blockIdx.x * 256 + threadIdx.x;
    int n0 = blockIdx.y * 128;
    float nd = nrmD[b*NN + m];
    float mx = -3.4e38f;
    for (int n = n0; n < n0 + 128; n++)
        mx = fmaxf(mx, inner[(long)b*NN*NN + (long)n*NN + m] / (nd * nrmS[b*NN + n] + EPSF));
    atomicMaxF(&maxSD[b*NN + m], mx);
}

// top-16 smallest from shared d2[NN], 256 threads
__device__ void select_topk(float* d2, int* outIdx) {
    __shared__ float rv[8];
    __shared__ int   ri[8];
    int tid = threadIdx.x, lane = tid & 31, w = tid >> 5;
    for (int kk = 0; kk < KK; kk++) {
        float best = 3.4e38f; int bi = 0;
        for (int m = tid; m < NN; m += 256) {
            float v = d2[m];
            if (v < best) { best = v; bi = m; }
        }
        #pragma unroll
        for (int o = 16; o > 0; o >>= 1) {
            float ov = __shfl_down_sync(0xffffffffu, best, o);
            int   oi = __shfl_down_sync(0xffffffffu, bi, o);
            if (ov < best || (ov == best && oi < bi)) { best = ov; bi = oi; }
        }
        if (lane == 0) { rv[w] = best; ri[w] = bi; }
        __syncthreads();
        if (tid == 0) {
            float bv = rv[0]; int bj = ri[0];
            #pragma unroll
            for (int i = 1; i < 8; i++)
                if (rv[i] < bv || (rv[i] == bv && ri[i] < bj)) { bv = rv[i]; bj = ri[i]; }
            outIdx[kk] = bj;
            d2[bj] = 3.4e38f;
        }
        __syncthreads();
    }
}

__global__ void k_knn_desc(const float* __restrict__ inner, const float* __restrict__ nsqS,
                           const float* __restrict__ nsqD, int* __restrict__ idxOut) {
    int n = blockIdx.x, b = blockIdx.y;
    __shared__ float d2[NN];
    const float* row = inner + (long)b*NN*NN + (long)n*NN;
    float q = nsqS[b*NN + n];
    for (int m = threadIdx.x; m < NN; m += 256) d2[m] = q + nsqD[b*NN + m] - 2.f * row[m];
    __syncthreads();
    select_topk(d2, idxOut + ((long)b*NN + n) * KK);
}

__global__ void k_knn_xyz(const float* __restrict__ xyz, int* __restrict__ idxOut) {
    int n = blockIdx.x, b = blockIdx.y;
    __shared__ float d2[NN];
    long base = (long)b * NN * 3;
    float qx = xyz[base + (long)n*3], qy = xyz[base + (long)n*3+1], qz = xyz[base + (long)n*3+2];
    float qq = qx*qx + qy*qy + qz*qz;
    for (int m = threadIdx.x; m < NN; m += 256) {
        float rx = xyz[base + (long)m*3], ry = xyz[base + (long)m*3+1], rz = xyz[base + (long)m*3+2];
        d2[m] = qq + rx*rx + ry*ry + rz*rz - 2.f*(qx*rx + qy*ry + qz*rz);
    }
    __syncthreads();
    select_topk(d2, idxOut + ((long)b*NN + n) * KK);
}

__global__ void k_simgather(const float* __restrict__ inner, const float* __restrict__ nrmS,
                            const float* __restrict__ nrmD, const float* __restrict__ maxDS,
                            const float* __restrict__ maxSD, const int* __restrict__ idx,
                            float* __restrict__ outSD, float* __restrict__ outDS) {
    int t = blockIdx.x * 256 + threadIdx.x;
    if (t >= PP) return;
    int b = t / (NN * KK);
    int n = (t / KK) & (NN - 1);
    int m = idx[t];
    float v  = inner[(long)b*NN*NN + (long)n*NN + m];
    float cs = v / (nrmD[b*NN + m] * nrmS[b*NN + n] + EPSF);
    outSD[t] = cs / (maxDS[b*NN + n] + EPSF);
    outDS[t] = cs / (maxSD[b*NN + m] + EPSF);
}

// nbr conv input: [knn_feats(C), rela(3), dist(1), pad(4)] stride 136
__global__ void k_build_nbr_f(const float* __restrict__ xyz, const float* __restrict__ dmat,
                              const int* __restrict__ idx, float* __restrict__ f) {
    int p = blockIdx.x;
    int n = (p / KK) & (NN - 1);
    int b = p / (NN * KK);
    int m = idx[p];
    const float* dr = dmat + ((long)b*NN + m) * CC;
    float* fo = f + (long)p * 136;
    int tid = threadIdx.x;
    fo[tid] = dr[tid];
    if (tid == 0) {
        long qb = ((long)b*NN + n) * 3, rb = ((long)b*NN + m) * 3;
        float rx = xyz[rb]-xyz[qb], ry = xyz[rb+1]-xyz[qb+1], rz = xyz[rb+2]-xyz[qb+2];
        fo[128] = rx; fo[129] = ry; fo[130] = rz; fo[131] = sqrtf(rx*rx+ry*ry+rz*rz);
        fo[132] = 0.f; fo[133] = 0.f; fo[134] = 0.f; fo[135] = 0.f;
    }
}

__global__ void k_nbr_final(const float* __restrict__ yraw, const float* __restrict__ sc,
                            const float* __restrict__ sh, const int* __restrict__ idx,
                            const float* __restrict__ dmat, float* __restrict__ outN) {
    int bn = blockIdx.x, tid = threadIdx.x; // 256
    __shared__ float fe[KK][CC];
    __shared__ float mk[KK], wgt[KK];
    __shared__ int sid[KK];
    if (tid < KK) sid[tid] = idx[(long)bn*KK + tid];
    for (int t = tid; t < KK * CC; t += 256) {
        int k = t >> 7, c = t & 127;
        float v = yraw[((long)bn*KK + k) * CC + c];
        fe[k][c] = fmaxf(v * sc[c] + sh[c], 0.f);
    }
    __syncthreads();
    int w = tid >> 5, lane = tid & 31;
    for (int kk = w; kk < KK; kk += 8) {
        float mx = -3.4e38f;
        for (int c = lane; c < CC; c += 32) mx = fmaxf(mx, fe[kk][c]);
        #pragma unroll
        for (int o = 16; o > 0; o >>= 1) mx = fmaxf(mx, __shfl_down_sync(0xffffffffu, mx, o));
        if (lane == 0) mk[kk] = mx;
    }
    __syncthreads();
    if (tid == 0) {
        float m = -3.4e38f;
        for (int k = 0; k < KK; k++) m = fmaxf(m, mk[k]);
        float s = 0.f;
        for (int k = 0; k < KK; k++) { float e = expf(mk[k]-m); wgt[k] = e; s += e; }
        float r = 1.f / s;
        for (int k = 0; k < KK; k++) wgt[k] *= r;
    }
    __syncthreads();
    if (tid < CC) {
        int b = bn >> 11;
        float a = 0.f;
        #pragma unroll
        for (int k = 0; k < KK; k++) a += wgt[k] * dmat[((long)b*NN + sid[k]) * CC + tid];
        outN[(long)bn*CC + tid] = a;
    }
}

// main feats build (272 ch)
__global__ void k_build_feats(const float* __restrict__ src_xyz, const float* __restrict__ dst_xyz,
                              const float* __restrict__ srcd, const float* __restrict__ dstd,
                              const float* __restrict__ srcw, const float* __restrict__ dstw,
                              const float* __restrict__ sdc, const float* __restrict__ dsc,
                              const float* __restrict__ sdn, const float* __restrict__ dsn,
                              const int* __restrict__ idx, float* __restrict__ feats) {
    int p = blockIdx.x;
    int n = (p / KK) & (NN - 1);
    int b = p / (NN * KK);
    int m = idx[p];
    float* fo = feats + (long)p * 272;
    int tid = threadIdx.x;
    fo[10 + tid]  = srcd[((long)b*NN + n) * CC + tid];
    fo[138 + tid] = dstd[((long)b*NN + m) * CC + tid];
    if (tid == 0) {
        long qb = ((long)b*NN + n) * 3, rb = ((long)b*NN + m) * 3;
        float sx = src_xyz[qb], sy = src_xyz[qb+1], sz = src_xyz[qb+2];
        float kx = dst_xyz[rb], ky = dst_xyz[rb+1], kz = dst_xyz[rb+2];
        float rx = kx-sx, ry = ky-sy, rz = kz-sz;
        fo[0]=rx; fo[1]=ry; fo[2]=rz; fo[3]=sqrtf(rx*rx+ry*ry+rz*rz);
        fo[4]=sx; fo[5]=sy; fo[6]=sz; fo[7]=kx; fo[8]=ky; fo[9]=kz;
        fo[266]=srcw[b*NN+n]; fo[267]=dstw[b*NN+m];
        fo[268]=sdc[p]; fo[269]=dsc[p]; fo[270]=sdn[p]; fo[271]=dsn[p];
    }
}

__global__ void k_attention(const float* __restrict__ yraw, const float* __restrict__ sc,
                            const float* __restrict__ sh, const int* __restrict__ idx,
                            const float* __restrict__ dst_xyz,
                            float* __restrict__ outC, float* __restrict__ att) {
    int bn = blockIdx.x, tid = threadIdx.x; // 256
    __shared__ float fe[KK][256];
    __shared__ float mk[KK], wgt[KK];
    __shared__ int sid[KK];
    if (tid < KK) sid[tid] = idx[(long)bn*KK + tid];
    float s = sc[tid], h = sh[tid];
    #pragma unroll
    for (int k = 0; k < KK; k++) {
        float v = yraw[((long)bn*KK + k) * 256 + tid];
        fe[k][tid] = fmaxf(v * s + h, 0.f);
    }
    __syncthreads();
    int w = tid >> 5, lane = tid & 31;
    for (int kk = w; kk < KK; kk += 8) {
        float mx = -3.4e38f;
        for (int c = lane; c < 256; c += 32) mx = fmaxf(mx, fe[kk][c]);
        #pragma unroll
        for (int o = 16; o > 0; o >>= 1) mx = fmaxf(mx, __shfl_down_sync(0xffffffffu, mx, o));
        if (lane == 0) mk[kk] = mx;
    }
    __syncthreads();
    if (tid == 0) {
        float m = -3.4e38f;
        for (int k = 0; k < KK; k++) m = fmaxf(m, mk[k]);
        float ssum = 0.f;
        for (int k = 0; k < KK; k++) { float e = expf(mk[k]-m); wgt[k] = e; ssum += e; }
        float r = 1.f / ssum;
        for (int k = 0; k < KK; k++) wgt[k] *= r;
    }
    __syncthreads();
    float a = 0.f;
    #pragma unroll
    for (int k = 0; k < KK; k++) a += wgt[k] * fe[k][tid];
    att[(long)bn * 256 + tid] = a;
    if (tid < 3) {
        int b = bn >> 11;
        float cg = 0.f;
        #pragma unroll
        for (int k = 0; k < KK; k++)
            cg += wgt[k] * dst_xyz[((long)b*NN + sid[k]) * 3 + tid];
        outC[(long)bn * 3 + tid] = cg;
    }
}

__global__ void k_mlp3(const float* __restrict__ yraw, const float* __restrict__ sc,
                       const float* __restrict__ sh, const float* __restrict__ w3,
                       const float* __restrict__ b3, float* __restrict__ outw) {
    int bn = blockIdx.x, tid = threadIdx.x; // 256
    float v = fmaxf(yraw[(long)bn*256 + tid] * sc[tid] + sh[tid], 0.f) * w3[tid];
    #pragma unroll
    for (int o = 16; o > 0; o >>= 1) v += __shfl_down_sync(0xffffffffu, v, o);
    __shared__ float ps[8];
    if ((tid & 31) == 0) ps[tid >> 5] = v;
    __syncthreads();
    if (tid == 0) {
        float s2 = 0.f;
        #pragma unroll
        for (int i = 0; i < 8; i++) s2 += ps[i];
        outw[bn] = 1.f / (1.f + expf(-(s2 + b3[0])));
    }
}

// ---------------- host side ----------------
static void conv_bn(const float* A, const float* W, float* Y, int P, int O, int Kd,
                    bool aff, const float* g, const float* bb,
                    float* statS, float* sc, float* sh) {
    k_gemm<<<dim3(O/BT, P/BT, 1), dim3(16, 16)>>>(A, W, Y, P, O, Kd, 0, 0, 0,
        aff ? sc : nullptr, aff ? sh : nullptr, statS, statS + 256);
    k_finalize<<<1, 256>>>(statS, statS + 256, g, bb, sc, sh, O, 1.f / (float)P);
}

extern "C" void kernel_launch(void* const* d_in, const int* in_sizes, int n_in,
                              void* d_out, int out_size) {
    const float* src_xyz  = (const float*)d_in[0];
    const float* src_desc = (const float*)d_in[1];
    const float* dst_xyz  = (const float*)d_in[2];
    const float* dst_desc = (const float*)d_in[3];
    const float* src_w    = (const float*)d_in[4];
    const float* dst_w    = (const float*)d_in[5];
    const float* c1_W0 = (const float*)d_in[6];
    const float* c1_W  = (const float*)d_in[7];
    const float* c1_g  = (const float*)d_in[8];
    const float* c1_b  = (const float*)d_in[9];
    const float* c2_W0 = (const float*)d_in[10];
    const float* c2_W  = (const float*)d_in[11];
    const float* c2_g  = (const float*)d_in[12];
    const float* c2_b  = (const float*)d_in[13];
    const float* m1_W  = (const float*)d_in[14];
    const float* m1_g  = (const float*)d_in[16];
    const float* m1_b  = (const float*)d_in[17];
    const float* m2_W  = (const float*)d_in[18];
    const float* m2_g  = (const float*)d_in[20];
    const float* m2_b  = (const float*)d_in[21];
    const float* m3_W  = (const float*)d_in[22];
    const float* m3_b  = (const float*)d_in[23];

    float* base = nullptr;
    cudaGetSymbolAddress((void**)&base, g_pool);
    float* srcd   = base + F_SRCD;
    float* dstd   = base + F_DSTD;
    float* nsqS   = base + F_NSQS;
    float* nsqD   = base + F_NSQD;
    float* nrmS   = base + F_NRMS;
    float* nrmD   = base + F_NRMD;
    float* maxDS  = base + F_MAXDS;
    float* maxSD  = base + F_MAXSD;
    float* nrm2S  = base + F_NRM2S;
    float* nrm2D  = base + F_NRM2D;
    float* sdc    = base + F_SDC;
    float* dsc    = base + F_DSC;
    float* sdn    = base + F_SDN;
    float* dsn    = base + F_DSN;
    float* statS  = base + F_STATS;
    float* sc     = base + F_SC;
    float* sh     = base + F_SH;
    float* w2p    = base + F_W2P;
    int*   idx    = (int*)(base + F_IDX);
    int*   sidx   = (int*)(base + F_SIDX);
    int*   didx   = (int*)(base + F_DIDX);
    float* att    = base + F_ATT;
    float* mb1    = base + F_MB1;
    float* mb2    = base + F_MB2;
    float* srcnbr = base + F_SRCNBR;
    float* dstnbr = base + F_DSTNBR;
    float* inner  = base + F_INNER;
    float* fbuf   = base + F_F;
    float* y0     = base + F_Y0;
    float* y1     = base + F_Y1;
    float* outC   = (float*)d_out;
    float* outW   = (float*)d_out + (long)BB*NN*3;

    // init: stats zero (finalize keeps them zeroed thereafter), padded weight
    k_fill<<<2, 256>>>(statS, 0.f, 512);
    k_pad_w<<<128, 136>>>(c2_W0, w2p);

    // A: transpose + norms
    k_transpose_norm<<<BN, 128>>>(src_desc, srcd, nsqS, nrmS);
    k_transpose_norm<<<BN, 128>>>(dst_desc, dstd, nsqD, nrmD);

    // inner = src . dst (per batch), then cos maxes + KNN + sims
    k_gemm<<<dim3(NN/BT, NN/BT, 2), dim3(16, 16)>>>(srcd, dstd, inner, NN, NN, CC,
        (long)NN*CC, (long)NN*CC, (long)NN*NN, nullptr, nullptr, nullptr, nullptr);
    k_fill<<<32, 256>>>(maxDS, -3.4e38f, 2*BN);
    k_rowmax<<<dim3(NN, BB), 256>>>(inner, nrmS, nrmD, maxDS);
    k_colmax<<<dim3(8, 16, 2), 256>>>(inner, nrmS, nrmD, maxSD);
    k_knn_desc<<<dim3(NN, BB), 256>>>(inner, nsqS, nsqD, idx);
    k_simgather<<<PP/256, 256>>>(inner, nrmS, nrmD, maxDS, maxSD, idx, sdc, dsc);

    // B: neighborhood descriptors (src then dst)
    k_knn_xyz<<<dim3(NN, BB), 256>>>(src_xyz, sidx);
    k_knn_xyz<<<dim3(NN, BB), 256>>>(dst_xyz, didx);
    const float* c2W1 = c2_W;
    const float* c2W2 = c2_W + CC*CC;
    for (int cloud = 0; cloud < 2; cloud++) {
        const float* xyz  = cloud ? dst_xyz : src_xyz;
        const float* dmat = cloud ? dstd : srcd;
        int* kidx         = cloud ? didx : sidx;
        float* outN       = cloud ? dstnbr : srcnbr;
        k_build_nbr_f<<<PP, 128>>>(xyz, dmat, kidx, fbuf);
        conv_bn(fbuf, w2p,  y0, PP, CC, 136, false, c2_g,        c2_b,        statS, sc, sh);
        conv_bn(y0,   c2W1, y1, PP, CC, CC,  true,  c2_g + CC,   c2_b + CC,   statS, sc, sh);
        conv_bn(y1,   c2W2, y0, PP, CC, CC,  true,  c2_g + 2*CC, c2_b + 2*CC, statS, sc, sh);
        k_nbr_final<<<BN, 256>>>(y0, sc, sh, kidx, dmat, outN);
    }

    // nbr cosine sims (reuse inner + maxes)
    k_rownorm<<<BN, 128>>>(srcnbr, nrm2S);
    k_rownorm<<<BN, 128>>>(dstnbr, nrm2D);
    k_gemm<<<dim3(NN/BT, NN/BT, 2), dim3(16, 16)>>>(srcnbr, dstnbr, inner, NN, NN, CC,
        (long)NN*CC, (long)NN*CC, (long)NN*NN, nullptr, nullptr, nullptr, nullptr);
    k_fill<<<32, 256>>>(maxDS, -3.4e38f, 2*BN);
    k_rowmax<<<dim3(NN, BB), 256>>>(inner, nrm2S, nrm2D, maxDS);
    k_colmax<<<dim3(8, 16, 2), 256>>>(inner, nrm2S, nrm2D, maxSD);
    k_simgather<<<PP/256, 256>>>(inner, nrm2S, nrm2D, maxDS, maxSD, idx, sdn, dsn);

    // C: main feature conv + attention
    k_build_feats<<<PP, 128>>>(src_xyz, dst_xyz, srcd, dstd, src_w, dst_w,
                               sdc, dsc, sdn, dsn, idx, fbuf);
    const float* c1W1 = c1_W;
    const float* c1W2 = c1_W + 256*256;
    conv_bn(fbuf, c1_W0, y0, PP, 256, 272, false, c1_g,        c1_b,        statS, sc, sh);
    conv_bn(y0,   c1W1,  y1, PP, 256, 256, true,  c1_g + 256,  c1_b + 256,  statS, sc, sh);
    conv_bn(y1,   c1W2,  y0, PP, 256, 256, true,  c1_g + 512,  c1_b + 512,  statS, sc, sh);
    k_attention<<<BN, 256>>>(y0, sc, sh, idx, dst_xyz, outC, att);

    // D: MLP head
    conv_bn(att, m1_W, mb1, BN, 256, 256, false, m1_g, m1_b, statS, sc, sh);
    conv_bn(mb1, m2_W, mb2, BN, 256, 256, true,  m2_g, m2_b, statS, sc, sh);
    k_mlp3<<<BN, 256>>>(mb2, sc, sh, m3_W, m3_b, outW);
}

// round 4
// speedup vs baseline: 1.5939x; 1.3097x over previous
#include <cuda_runtime.h>
#include <mma.h>
#include <math.h>
#include <float.h>

using namespace nvcuda;

#define BB 2
#define NN 2048
#define CC 128
#define KK 16
#define BN (BB*NN)
#define PP (BB*NN*KK)
#define EPSF 1e-6f
#define BNEPS 1e-5f

// ---------------- scratch pool ----------------
constexpr long F_SRCD   = 0;
constexpr long F_DSTD   = F_SRCD   + (long)BN*CC;
constexpr long F_NSQS   = F_DSTD   + (long)BN*CC;
constexpr long F_NSQD   = F_NSQS   + BN;
constexpr long F_NRMS   = F_NSQD   + BN;
constexpr long F_NRMD   = F_NRMS   + BN;
constexpr long F_MAXDS  = F_NRMD   + BN;
constexpr long F_MAXSD  = F_MAXDS  + BN;
constexpr long F_NRM2S  = F_MAXSD  + BN;
constexpr long F_NRM2D  = F_NRM2S  + BN;
constexpr long F_SDC    = F_NRM2D  + BN;
constexpr long F_DSC    = F_SDC    + PP;
constexpr long F_SDN    = F_DSC    + PP;
constexpr long F_DSN    = F_SDN    + PP;
constexpr long F_STATS  = F_DSN    + PP;   // 256 sum (contiguous with sumsq)
constexpr long F_STATQ  = F_STATS  + 256;
constexpr long F_SC     = F_STATQ  + 256;
constexpr long F_SH     = F_SC     + 256;
constexpr long F_W2P    = F_SH     + 256;          // padded c2_W0 [128][144]
constexpr long F_IDX    = F_W2P    + 128*144;      // int
constexpr long F_SIDX   = F_IDX    + PP;
constexpr long F_DIDX   = F_SIDX   + PP;
constexpr long F_ATT    = F_DIDX   + PP;
constexpr long F_MB1    = F_ATT    + (long)BN*256;
constexpr long F_MB2    = F_MB1    + (long)BN*256;
constexpr long F_SRCNBR = F_MB2    + (long)BN*256;
constexpr long F_DSTNBR = F_SRCNBR + (long)BN*CC;
constexpr long F_INNER  = F_DSTNBR + (long)BN*CC;
constexpr long F_F      = F_INNER  + (long)BB*NN*NN;
constexpr long F_Y0     = F_F      + (long)PP*272;
constexpr long F_Y1     = F_Y0     + (long)PP*256;
constexpr long F_END    = F_Y1     + (long)PP*256;

__device__ __align__(128) float g_pool[F_END];

__device__ __forceinline__ void atomicMaxF(float* a, float v) {
    if (!(v < 0.f)) atomicMax((int*)a, __float_as_int(v));
    else            atomicMin((unsigned int*)a, __float_as_uint(v));
}

__global__ void k_fill(float* __restrict__ p, float v, int n) {
    int i = blockIdx.x * blockDim.x + threadIdx.x;
    if (i < n) p[i] = v;
}

__global__ void k_pad_w(const float* __restrict__ W, float* __restrict__ Wp) {
    int o = blockIdx.x; int k = threadIdx.x; // 144 threads
    Wp[o * 144 + k] = (k < 132) ? W[o * 132 + k] : 0.f;
}

// [B,C,N] -> [B,N,C] plus |.|^2 and |.|
__global__ void k_transpose_norm(const float* __restrict__ desc, float* __restrict__ dmat,
                                 float* __restrict__ nsq, float* __restrict__ nrm) {
    int bn = blockIdx.x; int b = bn >> 11; int n = bn & (NN - 1);
    int c = threadIdx.x;
    float v = desc[((long)b*CC + c)*NN + n];
    dmat[(long)bn*CC + c] = v;
    float s = v * v;
    #pragma unroll
    for (int o = 16; o > 0; o >>= 1) s += __shfl_down_sync(0xffffffffu, s, o);
    __shared__ float ps[4];
    if ((c & 31) == 0) ps[c >> 5] = s;
    __syncthreads();
    if (c == 0) { float t = ps[0]+ps[1]+ps[2]+ps[3]; nsq[bn] = t; nrm[bn] = sqrtf(t); }
}

__global__ void k_rownorm(const float* __restrict__ dmat, float* __restrict__ nrm) {
    int bn = blockIdx.x; int c = threadIdx.x;
    float v = dmat[(long)bn*CC + c];
    float s = v * v;
    #pragma unroll
    for (int o = 16; o > 0; o >>= 1) s += __shfl_down_sync(0xffffffffu, s, o);
    __shared__ float ps[4];
    if ((c & 31) == 0) ps[c >> 5] = s;
    __syncthreads();
    if (c == 0) nrm[bn] = sqrtf(ps[0]+ps[1]+ps[2]+ps[3]);
}

// ---------------- fp32 SIMT GEMM (kept for KNN/cosine inner products) ----------------
#define BT 128
#define GKS 8
#define SPAD 4

__global__ __launch_bounds__(256)
void k_gemm(const float* __restrict__ A, const float* __restrict__ Bm,
            float* __restrict__ Cm, int P, int O, int Kd,
            long sA, long sB, long sC) {
    A  += (long)blockIdx.z * sA;
    Bm += (long)blockIdx.z * sB;
    Cm += (long)blockIdx.z * sC;
    __shared__ __align__(16) float As[2][GKS][BT + SPAD];
    __shared__ __align__(16) float Bs[2][GKS][BT + SPAD];
    const int tx = threadIdx.x, ty = threadIdx.y;
    const int tid = ty * 16 + tx;
    const int rowBase = blockIdx.y * BT;
    const int colBase = blockIdx.x * BT;
    const int lr = tid >> 1;
    const int lk = (tid & 1) * 4;
    const float* Aptr = A  + (long)(rowBase + lr) * Kd + lk;
    const float* Bptr = Bm + (long)(colBase + lr) * Kd + lk;
    float acc[8][8] = {};
    const int nk = Kd / GKS;
    {
        float4 av = *reinterpret_cast<const float4*>(Aptr);
        float4 bv = *reinterpret_cast<const float4*>(Bptr);
        As[0][lk+0][lr] = av.x; As[0][lk+1][lr] = av.y;
        As[0][lk+2][lr] = av.z; As[0][lk+3][lr] = av.w;
        Bs[0][lk+0][lr] = bv.x; Bs[0][lk+1][lr] = bv.y;
        Bs[0][lk+2][lr] = bv.z; Bs[0][lk+3][lr] = bv.w;
    }
    __syncthreads();
    for (int kt = 0; kt < nk; kt++) {
        const int cur = kt & 1;
        float4 av2, bv2;
        const bool more = (kt + 1 < nk);
        if (more) {
            av2 = *reinterpret_cast<const float4*>(Aptr + (kt+1)*GKS);
            bv2 = *reinterpret_cast<const float4*>(Bptr + (kt+1)*GKS);
        }
        #pragma unroll
        for (int kk = 0; kk < GKS; kk++) {
            float4 a0 = *reinterpret_cast<const float4*>(&As[cur][kk][ty*4]);
            float4 a1 = *reinterpret_cast<const float4*>(&As[cur][kk][ty*4+64]);
            float4 b0 = *reinterpret_cast<const float4*>(&Bs[cur][kk][tx*4]);
            float4 b1 = *reinterpret_cast<const float4*>(&Bs[cur][kk][tx*4+64]);
            float a[8] = {a0.x,a0.y,a0.z,a0.w,a1.x,a1.y,a1.z,a1.w};
            float b[8] = {b0.x,b0.y,b0.z,b0.w,b1.x,b1.y,b1.z,b1.w};
            #pragma unroll
            for (int i = 0; i < 8; i++)
                #pragma unroll
                for (int j = 0; j < 8; j++)
                    acc[i][j] += a[i] * b[j];
        }
        if (more) {
            const int nb = cur ^ 1;
            As[nb][lk+0][lr] = av2.x; As[nb][lk+1][lr] = av2.y;
            As[nb][lk+2][lr] = av2.z; As[nb][lk+3][lr] = av2.w;
            Bs[nb][lk+0][lr] = bv2.x; Bs[nb][lk+1][lr] = bv2.y;
            Bs[nb][lk+2][lr] = bv2.z; Bs[nb][lk+3][lr] = bv2.w;
        }
        __syncthreads();
    }
    #pragma unroll
    for (int i = 0; i < 8; i++) {
        long r = rowBase + ty*4 + ((i < 4) ? i : 64 + i - 4);
        float4 v0 = {acc[i][0], acc[i][1], acc[i][2], acc[i][3]};
        float4 v1 = {acc[i][4], acc[i][5], acc[i][6], acc[i][7]};
        *reinterpret_cast<float4*>(&Cm[r * O + colBase + tx*4])      = v0;
        *reinterpret_cast<float4*>(&Cm[r * O + colBase + tx*4 + 64]) = v1;
    }
}

// ---------------- TF32 tensor-core GEMM: C[P,O] = act(A)[P,K] * W[O,K]^T ----------------
// block tile 128x64, 8 warps (4 along M x 2 along N), warp tile 32x32 (2x2 wmma 16x16x8).
// Requires P%128==0, O%64==0, Kd%16==0. Fused input affine+ReLU and BN stat accumulation.
#define TCM 128
#define TCN 64
#define ALD 20          // A smem ld (16 + 4 pad)
#define CLD 68          // C smem ld (64 + 4 pad)

__global__ __launch_bounds__(256)
void k_gemm_tc(const float* __restrict__ A, const float* __restrict__ Bm,
               float* __restrict__ Cm, int P, int O, int Kd,
               const float* __restrict__ scA, const float* __restrict__ shA,
               float* __restrict__ statS, float* __restrict__ statQ) {
    __shared__ __align__(16) float smem[TCM * CLD];   // union: As+Bs during loop, Csm after
    float* As = smem;                 // [128][ALD]
    float* Bs = smem + TCM * ALD;     // [64][ALD]
    float* Csm = smem;                // [128][CLD]
    __shared__ float cs[TCN], cq[TCN];

    const int tid = threadIdx.x;
    const int wid = tid >> 5;
    const int wm = wid & 3;           // 0..3 along M
    const int wn = wid >> 2;          // 0..1 along N
    const int rowBase = blockIdx.y * TCM;
    const int colBase = blockIdx.x * TCN;
    const bool aff = (scA != nullptr);
    const bool stats = (statS != nullptr);

    if (stats && tid < TCN) { cs[tid] = 0.f; cq[tid] = 0.f; }

    wmma::fragment<wmma::accumulator, 16, 16, 8, float> c[2][2];
    #pragma unroll
    for (int i = 0; i < 2; i++)
        #pragma unroll
        for (int j = 0; j < 2; j++)
            wmma::fill_fragment(c[i][j], 0.f);

    const int nk = Kd / 16;
    for (int kc = 0; kc < nk; kc++) {
        const int k0 = kc * 16;
        // stage A (128x16) with optional affine+ReLU: 2 float4 per thread
        #pragma unroll
        for (int e = 0; e < 2; e++) {
            int lin = e * 256 + tid;
            int m = lin >> 2;
            int kq = (lin & 3) * 4;
            float4 v = *reinterpret_cast<const float4*>(&A[(long)(rowBase + m) * Kd + k0 + kq]);
            if (aff) {
                int gk = k0 + kq;
                v.x = fmaxf(v.x * scA[gk+0] + shA[gk+0], 0.f);
                v.y = fmaxf(v.y * scA[gk+1] + shA[gk+1], 0.f);
                v.z = fmaxf(v.z * scA[gk+2] + shA[gk+2], 0.f);
                v.w = fmaxf(v.w * scA[gk+3] + shA[gk+3], 0.f);
            }
            *reinterpret_cast<float4*>(&As[m * ALD + kq]) = v;
        }
        // stage B (64x16): 1 float4 per thread
        {
            int m = tid >> 2;
            int kq = (tid & 3) * 4;
            float4 v = *reinterpret_cast<const float4*>(&Bm[(long)(colBase + m) * Kd + k0 + kq]);
            *reinterpret_cast<float4*>(&Bs[m * ALD + kq]) = v;
        }
        __syncthreads();
        #pragma unroll
        for (int ks = 0; ks < 2; ks++) {
            wmma::fragment<wmma::matrix_a, 16, 16, 8, wmma::precision::tf32, wmma::row_major> a[2];
            wmma::fragment<wmma::matrix_b, 16, 16, 8, wmma::precision::tf32, wmma::col_major> b[2];
            #pragma unroll
            for (int i = 0; i < 2; i++) {
                wmma::load_matrix_sync(a[i], &As[(wm*32 + i*16) * ALD + ks*8], ALD);
                #pragma unroll
                for (int t = 0; t < a[i].num_elements; t++)
                    a[i].x[t] = wmma::__float_to_tf32(a[i].x[t]);
            }
            #pragma unroll
            for (int j = 0; j < 2; j++) {
                wmma::load_matrix_sync(b[j], &Bs[(wn*32 + j*16) * ALD + ks*8], ALD);
                #pragma unroll
                for (int t = 0; t < b[j].num_elements; t++)
                    b[j].x[t] = wmma::__float_to_tf32(b[j].x[t]);
            }
            #pragma unroll
            for (int i = 0; i < 2; i++)
                #pragma unroll
                for (int j = 0; j < 2; j++)
                    wmma::mma_sync(c[i][j], a[i], b[j], c[i][j]);
        }
        __syncthreads();
    }

    // stage C to smem for coalesced store + stats
    #pragma unroll
    for (int i = 0; i < 2; i++)
        #pragma unroll
        for (int j = 0; j < 2; j++)
            wmma::store_matrix_sync(&Csm[(wm*32 + i*16) * CLD + wn*32 + j*16], c[i][j],
                                    CLD, wmma::mem_row_major);
    __syncthreads();

    const int ccol = tid & 63;
    const int r0 = tid >> 6;
    float s = 0.f, q = 0.f;
    #pragma unroll 8
    for (int it = 0; it < 32; it++) {
        int r = r0 + it * 4;
        float v = Csm[r * CLD + ccol];
        Cm[(long)(rowBase + r) * O + colBase + ccol] = v;
        s += v; q += v * v;
    }
    if (stats) {
        atomicAdd(&cs[ccol], s);
        atomicAdd(&cq[ccol], q);
        __syncthreads();
        if (tid < TCN) {
            atomicAdd(&statS[colBase + tid], cs[tid]);
            atomicAdd(&statQ[colBase + tid], cq[tid]);
        }
    }
}

__global__ void k_finalize(const float* __restrict__ statSin, const float* __restrict__ statQin,
                           const float* __restrict__ g, const float* __restrict__ bb,
                           float* __restrict__ sc, float* __restrict__ sh, int O, float invP) {
    int o = blockIdx.x * blockDim.x + threadIdx.x;
    if (o < O) {
        float mu  = statSin[o] * invP;
        float var = fmaxf(statQin[o] * invP - mu * mu, 0.f);
        float s   = g[o] * rsqrtf(var + BNEPS);
        sc[o] = s;
        sh[o] = bb[o] - mu * s;
        ((float*)statSin)[o] = 0.f;
        ((float*)statQin)[o] = 0.f;
    }
}

// row maxes of cosine matrix
__global__ void k_rowmax(const float* __restrict__ inner, const float* __restrict__ nrmS,
                         const float* __restrict__ nrmD, float* __restrict__ maxDS) {
    int b = blockIdx.y, n = blockIdx.x;
    const float* row = inner + (long)b*NN*NN + (long)n*NN;
    float ns = nrmS[b*NN + n];
    float mx = -3.4e38f;
    for (int m = threadIdx.x; m < NN; m += 256)
        mx = fmaxf(mx, row[m] / (nrmD[b*NN + m] * ns + EPSF));
    #pragma unroll
    for (int o = 16; o > 0; o >>= 1) mx = fmaxf(mx, __shfl_down_sync(0xffffffffu, mx, o));
    __shared__ float ps[8];
    if ((threadIdx.x & 31) == 0) ps[threadIdx.x >> 5] = mx;
    __syncthreads();
    if (threadIdx.x == 0) {
        float r = ps[0];
        #pragma unroll
        for (int i = 1; i < 8; i++) r = fmaxf(r, ps[i]);
        maxDS[b*NN + n] = r;
    }
}

// col maxes, chunked over n
__global__ void k_colmax(const float* __restrict__ inner, const float* __restrict__ nrmS,
                         const float* __restrict__ nrmD, float* __restrict__ maxSD) {
    int b = blockIdx.z;
    int m = blockIdx.x * 256 + threadIdx.x;
    int n0 = blockIdx.y * 128;
    float nd = nrmD[b*NN + m];
    float mx = -3.4e38f;
    for (int n = n0; n < n0 + 128; n++)
        mx = fmaxf(mx, inner[(long)b*NN*NN + (long)n*NN + m] / (nd * nrmS[b*NN + n] + EPSF));
    atomicMaxF(&maxSD[b*NN + m], mx);
}

// top-16 smallest from shared d2[NN], 256 threads
__device__ void select_topk(float* d2, int* outIdx) {
    __shared__ float rv[8];
    __shared__ int   ri[8];
    int tid = threadIdx.x, lane = tid & 31, w = tid >> 5;
    for (int kk = 0; kk < KK; kk++) {
        float best = 3.4e38f; int bi = 0;
        for (int m = tid; m < NN; m += 256) {
            float v = d2[m];
            if (v < best) { best = v; bi = m; }
        }
        #pragma unroll
        for (int o = 16; o > 0; o >>= 1) {
            float ov = __shfl_down_sync(0xffffffffu, best, o);
            int   oi = __shfl_down_sync(0xffffffffu, bi, o);
            if (ov < best || (ov == best && oi < bi)) { best = ov; bi = oi; }
        }
        if (lane == 0) { rv[w] = best; ri[w] = bi; }
        __syncthreads();
        if (tid == 0) {
            float bv = rv[0]; int bj = ri[0];
            #pragma unroll
            for (int i = 1; i < 8; i++)
                if (rv[i] < bv || (rv[i] == bv && ri[i] < bj)) { bv = rv[i]; bj = ri[i]; }
            outIdx[kk] = bj;
            d2[bj] = 3.4e38f;
        }
        __syncthreads();
    }
}

__global__ void k_knn_desc(const float* __restrict__ inner, const float* __restrict__ nsqS,
                           const float* __restrict__ nsqD, int* __restrict__ idxOut) {
    int n = blockIdx.x, b = blockIdx.y;
    __shared__ float d2[NN];
    const float* row = inner + (long)b*NN*NN + (long)n*NN;
    float q = nsqS[b*NN + n];
    for (int m = threadIdx.x; m < NN; m += 256) d2[m] = q + nsqD[b*NN + m] - 2.f * row[m];
    __syncthreads();
    select_topk(d2, idxOut + ((long)b*NN + n) * KK);
}

__global__ void k_knn_xyz(const float* __restrict__ xyz, int* __restrict__ idxOut) {
    int n = blockIdx.x, b = blockIdx.y;
    __shared__ float d2[NN];
    long base = (long)b * NN * 3;
    float qx = xyz[base + (long)n*3], qy = xyz[base + (long)n*3+1], qz = xyz[base + (long)n*3+2];
    float qq = qx*qx + qy*qy + qz*qz;
    for (int m = threadIdx.x; m < NN; m += 256) {
        float rx = xyz[base + (long)m*3], ry = xyz[base + (long)m*3+1], rz = xyz[base + (long)m*3+2];
        d2[m] = qq + rx*rx + ry*ry + rz*rz - 2.f*(qx*rx + qy*ry + qz*rz);
    }
    __syncthreads();
    select_topk(d2, idxOut + ((long)b*NN + n) * KK);
}

__global__ void k_simgather(const float* __restrict__ inner, const float* __restrict__ nrmS,
                            const float* __restrict__ nrmD, const float* __restrict__ maxDS,
                            const float* __restrict__ maxSD, const int* __restrict__ idx,
                            float* __restrict__ outSD, float* __restrict__ outDS) {
    int t = blockIdx.x * 256 + threadIdx.x;
    if (t >= PP) return;
    int b = t / (NN * KK);
    int n = (t / KK) & (NN - 1);
    int m = idx[t];
    float v  = inner[(long)b*NN*NN + (long)n*NN + m];
    float cs = v / (nrmD[b*NN + m] * nrmS[b*NN + n] + EPSF);
    outSD[t] = cs / (maxDS[b*NN + n] + EPSF);
    outDS[t] = cs / (maxSD[b*NN + m] + EPSF);
}

// nbr conv input: [knn_feats(C), rela(3), dist(1), pad(8)] stride 144
__global__ void k_build_nbr_f(const float* __restrict__ xyz, const float* __restrict__ dmat,
                              const int* __restrict__ idx, float* __restrict__ f) {
    int p = blockIdx.x;
    int n = (p / KK) & (NN - 1);
    int b = p / (NN * KK);
    int m = idx[p];
    const float* dr = dmat + ((long)b*NN + m) * CC;
    float* fo = f + (long)p * 144;
    int tid = threadIdx.x;
    fo[tid] = dr[tid];
    if (tid == 0) {
        long qb = ((long)b*NN + n) * 3, rb = ((long)b*NN + m) * 3;
        float rx = xyz[rb]-xyz[qb], ry = xyz[rb+1]-xyz[qb+1], rz = xyz[rb+2]-xyz[qb+2];
        fo[128] = rx; fo[129] = ry; fo[130] = rz; fo[131] = sqrtf(rx*rx+ry*ry+rz*rz);
        #pragma unroll
        for (int z = 132; z < 144; z++) fo[z] = 0.f;
    }
}

__global__ void k_nbr_final(const float* __restrict__ yraw, const float* __restrict__ sc,
                            const float* __restrict__ sh, const int* __restrict__ idx,
                            const float* __restrict__ dmat, float* __restrict__ outN) {
    int bn = blockIdx.x, tid = threadIdx.x; // 256
    __shared__ float fe[KK][CC];
    __shared__ float mk[KK], wgt[KK];
    __shared__ int sid[KK];
    if (tid < KK) sid[tid] = idx[(long)bn*KK + tid];
    for (int t = tid; t < KK * CC; t += 256) {
        int k = t >> 7, c = t & 127;
        float v = yraw[((long)bn*KK + k) * CC + c];
        fe[k][c] = fmaxf(v * sc[c] + sh[c], 0.f);
    }
    __syncthreads();
    int w = tid >> 5, lane = tid & 31;
    for (int kk = w; kk < KK; kk += 8) {
        float mx = -3.4e38f;
        for (int c = lane; c < CC; c += 32) mx = fmaxf(mx, fe[kk][c]);
        #pragma unroll
        for (int o = 16; o > 0; o >>= 1) mx = fmaxf(mx, __shfl_down_sync(0xffffffffu, mx, o));
        if (lane == 0) mk[kk] = mx;
    }
    __syncthreads();
    if (tid == 0) {
        float m = -3.4e38f;
        for (int k = 0; k < KK; k++) m = fmaxf(m, mk[k]);
        float s = 0.f;
        for (int k = 0; k < KK; k++) { float e = expf(mk[k]-m); wgt[k] = e; s += e; }
        float r = 1.f / s;
        for (int k = 0; k < KK; k++) wgt[k] *= r;
    }
    __syncthreads();
    if (tid < CC) {
        int b = bn >> 11;
        float a = 0.f;
        #pragma unroll
        for (int k = 0; k < KK; k++) a += wgt[k] * dmat[((long)b*NN + sid[k]) * CC + tid];
        outN[(long)bn*CC + tid] = a;
    }
}

// main feats build (272 ch)
__global__ void k_build_feats(const float* __restrict__ src_xyz, const float* __restrict__ dst_xyz,
                              const float* __restrict__ srcd, const float* __restrict__ dstd,
                              const float* __restrict__ srcw, const float* __restrict__ dstw,
                              const float* __restrict__ sdc, const float* __restrict__ dsc,
                              const float* __restrict__ sdn, const float* __restrict__ dsn,
                              const int* __restrict__ idx, float* __restrict__ feats) {
    int p = blockIdx.x;
    int n = (p / KK) & (NN - 1);
    int b = p / (NN * KK);
    int m = idx[p];
    float* fo = feats + (long)p * 272;
    int tid = threadIdx.x;
    fo[10 + tid]  = srcd[((long)b*NN + n) * CC + tid];
    fo[138 + tid] = dstd[((long)b*NN + m) * CC + tid];
    if (tid == 0) {
        long qb = ((long)b*NN + n) * 3, rb = ((long)b*NN + m) * 3;
        float sx = src_xyz[qb], sy = src_xyz[qb+1], sz = src_xyz[qb+2];
        float kx = dst_xyz[rb], ky = dst_xyz[rb+1], kz = dst_xyz[rb+2];
        float rx = kx-sx, ry = ky-sy, rz = kz-sz;
        fo[0]=rx; fo[1]=ry; fo[2]=rz; fo[3]=sqrtf(rx*rx+ry*ry+rz*rz);
        fo[4]=sx; fo[5]=sy; fo[6]=sz; fo[7]=kx; fo[8]=ky; fo[9]=kz;
        fo[266]=srcw[b*NN+n]; fo[267]=dstw[b*NN+m];
        fo[268]=sdc[p]; fo[269]=dsc[p]; fo[270]=sdn[p]; fo[271]=dsn[p];
    }
}

__global__ void k_attention(const float* __restrict__ yraw, const float* __restrict__ sc,
                            const float* __restrict__ sh, const int* __restrict__ idx,
                            const float* __restrict__ dst_xyz,
                            float* __restrict__ outC, float* __restrict__ att) {
    int bn = blockIdx.x, tid = threadIdx.x; // 256
    __shared__ float fe[KK][256];
    __shared__ float mk[KK], wgt[KK];
    __shared__ int sid[KK];
    if (tid < KK) sid[tid] = idx[(long)bn*KK + tid];
    float s = sc[tid], h = sh[tid];
    #pragma unroll
    for (int k = 0; k < KK; k++) {
        float v = yraw[((long)bn*KK + k) * 256 + tid];
        fe[k][tid] = fmaxf(v * s + h, 0.f);
    }
    __syncthreads();
    int w = tid >> 5, lane = tid & 31;
    for (int kk = w; kk < KK; kk += 8) {
        float mx = -3.4e38f;
        for (int c = lane; c < 256; c += 32) mx = fmaxf(mx, fe[kk][c]);
        #pragma unroll
        for (int o = 16; o > 0; o >>= 1) mx = fmaxf(mx, __shfl_down_sync(0xffffffffu, mx, o));
        if (lane == 0) mk[kk] = mx;
    }
    __syncthreads();
    if (tid == 0) {
        float m = -3.4e38f;
        for (int k = 0; k < KK; k++) m = fmaxf(m, mk[k]);
        float ssum = 0.f;
        for (int k = 0; k < KK; k++) { float e = expf(mk[k]-m); wgt[k] = e; ssum += e; }
        float r = 1.f / ssum;
        for (int k = 0; k < KK; k++) wgt[k] *= r;
    }
    __syncthreads();
    float a = 0.f;
    #pragma unroll
    for (int k = 0; k < KK; k++) a += wgt[k] * fe[k][tid];
    att[(long)bn * 256 + tid] = a;
    if (tid < 3) {
        int b = bn >> 11;
        float cg = 0.f;
        #pragma unroll
        for (int k = 0; k < KK; k++)
            cg += wgt[k] * dst_xyz[((long)b*NN + sid[k]) * 3 + tid];
        outC[(long)bn * 3 + tid] = cg;
    }
}

__global__ void k_mlp3(const float* __restrict__ yraw, const float* __restrict__ sc,
                       const float* __restrict__ sh, const float* __restrict__ w3,
                       const float* __restrict__ b3, float* __restrict__ outw) {
    int bn = blockIdx.x, tid = threadIdx.x; // 256
    float v = fmaxf(yraw[(long)bn*256 + tid] * sc[tid] + sh[tid], 0.f) * w3[tid];
    #pragma unroll
    for (int o = 16; o > 0; o >>= 1) v += __shfl_down_sync(0xffffffffu, v, o);
    __shared__ float ps[8];
    if ((tid & 31) == 0) ps[tid >> 5] = v;
    __syncthreads();
    if (tid == 0) {
        float s2 = 0.f;
        #pragma unroll
        for (int i = 0; i < 8; i++) s2 += ps[i];
        outw[bn] = 1.f / (1.f + expf(-(s2 + b3[0])));
    }
}

// ---------------- host side ----------------
static void conv_bn(const float* A, const float* W, float* Y, int P, int O, int Kd,
                    bool aff, const float* g, const float* bb,
                    float* statS, float* sc, float* sh) {
    k_gemm_tc<<<dim3(O/TCN, P/TCM), 256>>>(A, W, Y, P, O, Kd,
        aff ? sc : nullptr, aff ? sh : nullptr, statS, statS + 256);
    k_finalize<<<1, 256>>>(statS, statS + 256, g, bb, sc, sh, O, 1.f / (float)P);
}

extern "C" void kernel_launch(void* const* d_in, const int* in_sizes, int n_in,
                              void* d_out, int out_size) {
    const float* src_xyz  = (const float*)d_in[0];
    const float* src_desc = (const float*)d_in[1];
    const float* dst_xyz  = (const float*)d_in[2];
    const float* dst_desc = (const float*)d_in[3];
    const float* src_w    = (const float*)d_in[4];
    const float* dst_w    = (const float*)d_in[5];
    const float* c1_W0 = (const float*)d_in[6];
    const float* c1_W  = (const float*)d_in[7];
    const float* c1_g  = (const float*)d_in[8];
    const float* c1_b  = (const float*)d_in[9];
    const float* c2_W0 = (const float*)d_in[10];
    const float* c2_W  = (const float*)d_in[11];
    const float* c2_g  = (const float*)d_in[12];
    const float* c2_b  = (const float*)d_in[13];
    const float* m1_W  = (const float*)d_in[14];
    const float* m1_g  = (const float*)d_in[16];
    const float* m1_b  = (const float*)d_in[17];
    const float* m2_W  = (const float*)d_in[18];
    const float* m2_g  = (const float*)d_in[20];
    const float* m2_b  = (const float*)d_in[21];
    const float* m3_W  = (const float*)d_in[22];
    const float* m3_b  = (const float*)d_in[23];

    float* base = nullptr;
    cudaGetSymbolAddress((void**)&base, g_pool);
    float* srcd   = base + F_SRCD;
    float* dstd   = base + F_DSTD;
    float* nsqS   = base + F_NSQS;
    float* nsqD   = base + F_NSQD;
    float* nrmS   = base + F_NRMS;
    float* nrmD   = base + F_NRMD;
    float* maxDS  = base + F_MAXDS;
    float* maxSD  = base + F_MAXSD;
    float* nrm2S  = base + F_NRM2S;
    float* nrm2D  = base + F_NRM2D;
    float* sdc    = base + F_SDC;
    float* dsc    = base + F_DSC;
    float* sdn    = base + F_SDN;
    float* dsn    = base + F_DSN;
    float* statS  = base + F_STATS;
    float* sc     = base + F_SC;
    float* sh     = base + F_SH;
    float* w2p    = base + F_W2P;
    int*   idx    = (int*)(base + F_IDX);
    int*   sidx   = (int*)(base + F_SIDX);
    int*   didx   = (int*)(base + F_DIDX);
    float* att    = base + F_ATT;
    float* mb1    = base + F_MB1;
    float* mb2    = base + F_MB2;
    float* srcnbr = base + F_SRCNBR;
    float* dstnbr = base + F_DSTNBR;
    float* inner  = base + F_INNER;
    float* fbuf   = base + F_F;
    float* y0     = base + F_Y0;
    float* y1     = base + F_Y1;
    float* outC   = (float*)d_out;
    float* outW   = (float*)d_out + (long)BB*NN*3;

    k_fill<<<2, 256>>>(statS, 0.f, 512);
    k_pad_w<<<128, 144>>>(c2_W0, w2p);

    // A: transpose + norms
    k_transpose_norm<<<BN, 128>>>(src_desc, srcd, nsqS, nrmS);
    k_transpose_norm<<<BN, 128>>>(dst_desc, dstd, nsqD, nrmD);

    // inner = src . dst (fp32, feeds KNN selection) + cos maxes + sims
    k_gemm<<<dim3(NN/BT, NN/BT, 2), dim3(16, 16)>>>(srcd, dstd, inner, NN, NN, CC,
        (long)NN*CC, (long)NN*CC, (long)NN*NN);
    k_fill<<<32, 256>>>(maxDS, -3.4e38f, 2*BN);
    k_rowmax<<<dim3(NN, BB), 256>>>(inner, nrmS, nrmD, maxDS);
    k_colmax<<<dim3(8, 16, 2), 256>>>(inner, nrmS, nrmD, maxSD);
    k_knn_desc<<<dim3(NN, BB), 256>>>(inner, nsqS, nsqD, idx);
    k_simgather<<<PP/256, 256>>>(inner, nrmS, nrmD, maxDS, maxSD, idx, sdc, dsc);

    // B: neighborhood descriptors
    k_knn_xyz<<<dim3(NN, BB), 256>>>(src_xyz, sidx);
    k_knn_xyz<<<dim3(NN, BB), 256>>>(dst_xyz, didx);
    const float* c2W1 = c2_W;
    const float* c2W2 = c2_W + CC*CC;
    for (int cloud = 0; cloud < 2; cloud++) {
        const float* xyz  = cloud ? dst_xyz : src_xyz;
        const float* dmat = cloud ? dstd : srcd;
        int* kidx         = cloud ? didx : sidx;
        float* outN       = cloud ? dstnbr : srcnbr;
        k_build_nbr_f<<<PP, 128>>>(xyz, dmat, kidx, fbuf);
        conv_bn(fbuf, w2p,  y0, PP, CC, 144, false, c2_g,        c2_b,        statS, sc, sh);
        conv_bn(y0,   c2W1, y1, PP, CC, CC,  true,  c2_g + CC,   c2_b + CC,   statS, sc, sh);
        conv_bn(y1,   c2W2, y0, PP, CC, CC,  true,  c2_g + 2*CC, c2_b + 2*CC, statS, sc, sh);
        k_nbr_final<<<BN, 256>>>(y0, sc, sh, kidx, dmat, outN);
    }

    // nbr cosine sims (fp32 inner)
    k_rownorm<<<BN, 128>>>(srcnbr, nrm2S);
    k_rownorm<<<BN, 128>>>(dstnbr, nrm2D);
    k_gemm<<<dim3(NN/BT, NN/BT, 2), dim3(16, 16)>>>(srcnbr, dstnbr, inner, NN, NN, CC,
        (long)NN*CC, (long)NN*CC, (long)NN*NN);
    k_fill<<<32, 256>>>(maxDS, -3.4e38f, 2*BN);
    k_rowmax<<<dim3(NN, BB), 256>>>(inner, nrm2S, nrm2D, maxDS);
    k_colmax<<<dim3(8, 16, 2), 256>>>(inner, nrm2S, nrm2D, maxSD);
    k_simgather<<<PP/256, 256>>>(inner, nrm2S, nrm2D, maxDS, maxSD, idx, sdn, dsn);

    // C: main feature conv + attention
    k_build_feats<<<PP, 128>>>(src_xyz, dst_xyz, srcd, dstd, src_w, dst_w,
                               sdc, dsc, sdn, dsn, idx, fbuf);
    const float* c1W1 = c1_W;
    const float* c1W2 = c1_W + 256*256;
    conv_bn(fbuf, c1_W0, y0, PP, 256, 272, false, c1_g,        c1_b,        statS, sc, sh);
    conv_bn(y0,   c1W1,  y1, PP, 256, 256, true,  c1_g + 256,  c1_b + 256,  statS, sc, sh);
    conv_bn(y1,   c1W2,  y0, PP, 256, 256, true,  c1_g + 512,  c1_b + 512,  statS, sc, sh);
    k_attention<<<BN, 256>>>(y0, sc, sh, idx, dst_xyz, outC, att);

    // D: MLP head
    conv_bn(att, m1_W, mb1, BN, 256, 256, false, m1_g, m1_b, statS, sc, sh);
    conv_bn(mb1, m2_W, mb2, BN, 256, 256, true,  m2_g, m2_b, statS, sc, sh);
    k_mlp3<<<BN, 256>>>(mb2, sc, sh, m3_W, m3_b, outW);
}